// round 10
// baseline (speedup 1.0000x reference)
#include <cuda_runtime.h>
#include <cuda_fp16.h>
#include <cuda_bf16.h>
#include <mma.h>
#include <cstdint>

#define N_NODES 20000
#define BATCH   4
#define H_DIM   128
#define I_DIM   64
#define E_CAP   320000
#define NODEVEC 512                       /* halves per node, [b][h] */
#define BNH     (BATCH * N_NODES * H_DIM)
#define SCAN_BLKS 20
#define SA_STRIDE 136                     /* smem stride (elems), mult of 8 */
#define FAT_SMEM  (128 * SA_STRIDE * 4)   /* 69632 B: 2 bf16 tiles OR 1 f32 tile */

typedef unsigned long long ull;
using namespace nvcuda;

/* ---------------- device scratch (static, allocation-free) -------------- */
__device__ __align__(16) __half g_hwh[(size_t)N_NODES * NODEVEC]; /* h@Wg (unscaled), fp16 */
__device__ __align__(16) __nv_bfloat16 g_Bbf[H_DIM * H_DIM];      /* bf16(Wg), [k][n] row-major */
__device__ int   g_outcnt[N_NODES];
__device__ int   g_incnt[N_NODES];
__device__ int   g_cursor[N_NODES];
__device__ int   g_off[N_NODES + 1];
__device__ __align__(8) int2 g_cedge[E_CAP];       /* {src, bits(dn_src[src])} */
__device__ float g_dnsrc[N_NODES];
__device__ float g_dndst[N_NODES];
__device__ int   g_bsum[SCAN_BLKS];
__device__ int   g_bpre[SCAN_BLKS + 1];
__device__ int   g_flagA, g_flagB, g_flagC;
__device__ __align__(16) float g_gates[4 * BATCH * H_DIM];        /* [gate][b][h] */

/* ---------------- helpers ---------------------------------------------- */
__device__ __forceinline__ float tanh_hw(float x) {
    float y;
    asm("tanh.approx.f32 %0, %1;" : "=f"(y) : "f"(x));
    return y;
}
__device__ __forceinline__ float sig_hw(float x) {
    return fmaf(tanh_hw(0.5f * x), 0.5f, 0.5f);
}

/* ---------------- K0: zero counters + build bf16(Wg) -------------------- */
__global__ void k_zero(const float* __restrict__ Wg) {
    int i = blockIdx.x * blockDim.x + threadIdx.x;
    if (i < N_NODES) { g_outcnt[i] = 0; g_incnt[i] = 0; }
    if (i == 0) { g_flagA = 0; g_flagB = 0; g_flagC = 0; }
    if (i < H_DIM * H_DIM) g_Bbf[i] = __float2bfloat16(Wg[i]);
}

/* ---------------- K1 (fat): deg || gates || mm(wmma bf16) ----------------
   256 threads/block. grid = 946:
     bid < 626 : even -> mm tile bid/2 ; odd -> deg block (bid-1)/2
     626..937  : mm tile 313 + (bid-626)
     938..945  : gates block bid-938
------------------------------------------------------------------------- */
__global__ void __launch_bounds__(256) k_fat(
        const float* __restrict__ hprev,
        const int* __restrict__ src, const int* __restrict__ dst, int E,
        const float* __restrict__ x,
        const float* __restrict__ Wi, const float* __restrict__ bi,
        const float* __restrict__ Wf, const float* __restrict__ bf,
        const float* __restrict__ Wo, const float* __restrict__ bo,
        const float* __restrict__ Wc, const float* __restrict__ bc) {
    extern __shared__ unsigned char dsm[];
    int bid = blockIdx.x;
    int t = threadIdx.x;

    int role, rid;                 /* 0=mm 1=deg 2=gates */
    if (bid < 626) {
        if (bid & 1) { role = 1; rid = (bid - 1) >> 1; }
        else         { role = 0; rid = bid >> 1; }
    } else if (bid < 938) { role = 0; rid = 313 + (bid - 626); }
    else                  { role = 2; rid = bid - 938; }

    if (role == 1) {
        /* -------- degree histograms, 4 edges / thread -------- */
        int i = rid * 256 + t;
        int E4 = E >> 2;
        if (i < E4) {
            int4 s = ((const int4*)src)[i];
            int4 d = ((const int4*)dst)[i];
            atomicAdd(&g_outcnt[s.x], 1); atomicAdd(&g_outcnt[s.y], 1);
            atomicAdd(&g_outcnt[s.z], 1); atomicAdd(&g_outcnt[s.w], 1);
            atomicAdd(&g_incnt[d.x], 1);  atomicAdd(&g_incnt[d.y], 1);
            atomicAdd(&g_incnt[d.z], 1);  atomicAdd(&g_incnt[d.w], 1);
        }
        int e = E4 * 4 + i;
        if (e < E) { atomicAdd(&g_outcnt[src[e]], 1); atomicAdd(&g_incnt[dst[e]], 1); }
        return;
    }

    if (role == 2) {
        /* -------- tiny gate GEMVs  x@W + b -------- */
        int tid = rid * 256 + t;
        int g = tid / (BATCH * H_DIM);
        int b = (tid % (BATCH * H_DIM)) / H_DIM;
        int j = tid % H_DIM;
        const float* W; const float* bb;
        switch (g) {
            case 0:  W = Wi; bb = bi; break;
            case 1:  W = Wf; bb = bf; break;
            case 2:  W = Wo; bb = bo; break;
            default: W = Wc; bb = bc; break;
        }
        float s = bb[j];
        const float* xr = x + b * I_DIM;
#pragma unroll 8
        for (int k = 0; k < I_DIM; k++) s += xr[k] * W[k * H_DIM + j];
        g_gates[tid] = s;
        return;
    }

    /* -------- mm: g_hwh[tile rows] = bf16(h_prev) @ bf16(Wg) via HMMA ---- */
    {
        __nv_bfloat16* sA = (__nv_bfloat16*)dsm;                  /* 128 x 136 */
        __nv_bfloat16* sB = sA + 128 * SA_STRIDE;                 /* 128 x 136 */
        float*         sC = (float*)dsm;                          /* reuse      */

        int w   = t >> 5;                    /* warp 0..7: rows [16w,16w+16) */
        int r0  = rid * 128;

        /* A tile: 128 rows x 128 k fp32 -> bf16, stride 136 */
        {
            const float4* h4 = (const float4*)hprev;
#pragma unroll
            for (int i = 0; i < 16; i++) {
                int idx = t + i * 256;       /* 4096 float4 */
                int row = idx >> 5;
                int kq  = idx & 31;
                float4 v = h4[(size_t)(r0 + row) * 32 + kq];
                __nv_bfloat162 b01 = __floats2bfloat162_rn(v.x, v.y);
                __nv_bfloat162 b23 = __floats2bfloat162_rn(v.z, v.w);
                uint2 st;
                st.x = reinterpret_cast<unsigned&>(b01);
                st.y = reinterpret_cast<unsigned&>(b23);
                *(uint2*)&sA[row * SA_STRIDE + kq * 4] = st;
            }
        }
        /* B tile: bf16(Wg) [k][n], global stride 128 -> smem stride 136 */
        {
            const uint2* gb = (const uint2*)g_Bbf;                /* 4096 x 4 bf16 */
#pragma unroll
            for (int i = 0; i < 16; i++) {
                int idx = t + i * 256;
                int row = idx >> 5;
                int c4  = idx & 31;
                *(uint2*)&sB[row * SA_STRIDE + c4 * 4] = gb[idx];
            }
        }
        __syncthreads();

        wmma::fragment<wmma::accumulator, 16, 16, 16, float> acc[8];
#pragma unroll
        for (int nc = 0; nc < 8; nc++) wmma::fill_fragment(acc[nc], 0.0f);

        wmma::fragment<wmma::matrix_a, 16, 16, 16, __nv_bfloat16, wmma::row_major> af;
        wmma::fragment<wmma::matrix_b, 16, 16, 16, __nv_bfloat16, wmma::row_major> bf_;
#pragma unroll
        for (int ks = 0; ks < 8; ks++) {
            wmma::load_matrix_sync(af, &sA[(w * 16) * SA_STRIDE + ks * 16], SA_STRIDE);
#pragma unroll
            for (int nc = 0; nc < 8; nc++) {
                wmma::load_matrix_sync(bf_, &sB[(ks * 16) * SA_STRIDE + nc * 16], SA_STRIDE);
                wmma::mma_sync(acc[nc], af, bf_, acc[nc]);
            }
        }
        __syncthreads();                    /* done reading sA/sB */

#pragma unroll
        for (int nc = 0; nc < 8; nc++)
            wmma::store_matrix_sync(&sC[(w * 16) * SA_STRIDE + nc * 16], acc[nc],
                                    SA_STRIDE, wmma::mem_row_major);
        __syncthreads();

        /* write out as fp16: thread t -> row t>>1, cols [(t&1)*64, +64) */
        {
            int row = t >> 1;
            int c0  = (t & 1) * 64;
            int m = r0 + row;
            int b = m / N_NODES;
            int n = m - b * N_NODES;
            __half* dstp = g_hwh + (size_t)n * NODEVEC + b * H_DIM + c0;
            const float* srcp = &sC[row * SA_STRIDE + c0];
#pragma unroll
            for (int q = 0; q < 8; q++) {
                float4 v0 = *(const float4*)&srcp[q * 8];
                float4 v1 = *(const float4*)&srcp[q * 8 + 4];
                __half2 h0 = __floats2half2_rn(v0.x, v0.y);
                __half2 h1 = __floats2half2_rn(v0.z, v0.w);
                __half2 h2 = __floats2half2_rn(v1.x, v1.y);
                __half2 h3 = __floats2half2_rn(v1.z, v1.w);
                uint4 st;
                st.x = reinterpret_cast<unsigned&>(h0);
                st.y = reinterpret_cast<unsigned&>(h1);
                st.z = reinterpret_cast<unsigned&>(h2);
                st.w = reinterpret_cast<unsigned&>(h3);
                *(uint4*)(dstp + q * 8) = st;
            }
        }
    }
}

/* ---------------- K2: fused scan + CSR fill (20 co-resident blocks) ----- */
__global__ void __launch_bounds__(1024) k_scanfill(const int* __restrict__ src,
                                                   const int* __restrict__ dst, int E) {
    __shared__ int sm[1024];
    int bid = blockIdx.x;
    int t = threadIdx.x;
    int idx = bid * 1024 + t;
    int cnt = (idx < N_NODES) ? g_incnt[idx] : 0;

    /* phase 1: block sum */
    sm[t] = cnt;
    __syncthreads();
#pragma unroll
    for (int s = 512; s; s >>= 1) {
        if (t < s) sm[t] += sm[t + s];
        __syncthreads();
    }
    if (t == 0) {
        g_bsum[bid] = sm[0];
        __threadfence();
        atomicAdd(&g_flagA, 1);
    }

    /* phase 2: block 0 scans the 20 partials */
    if (bid == 0 && t == 0) {
        while (*((volatile int*)&g_flagA) < SCAN_BLKS) { }
        __threadfence();
        int run = 0;
        for (int b = 0; b < SCAN_BLKS; b++) {
            g_bpre[b] = run;
            run += *((volatile int*)&g_bsum[b]);
        }
        g_off[N_NODES] = run;
        __threadfence();
        atomicExch(&g_flagB, 1);
    }
    if (t == 0) {
        while (*((volatile int*)&g_flagB) == 0) { }
    }
    __syncthreads();
    int base = *((volatile int*)&g_bpre[bid]);

    /* phase 3: intra-block inclusive scan + norms + cursor zero */
    sm[t] = cnt;
    __syncthreads();
#pragma unroll
    for (int off = 1; off < 1024; off <<= 1) {
        int u = (t >= off) ? sm[t - off] : 0;
        __syncthreads();
        sm[t] += u;
        __syncthreads();
    }
    if (idx < N_NODES) {
        int incl = sm[t];
        g_off[idx]    = base + incl - cnt;
        g_dndst[idx]  = rsqrtf((float)max(cnt, 1));
        g_dnsrc[idx]  = rsqrtf((float)max(g_outcnt[idx], 1));
        g_cursor[idx] = 0;
    }

    /* grid-wide barrier: all offsets/norms/cursors visible */
    __syncthreads();
    if (t == 0) {
        __threadfence();
        atomicAdd(&g_flagC, 1);
        while (*((volatile int*)&g_flagC) < SCAN_BLKS) { }
        __threadfence();
    }
    __syncthreads();

    /* phase 4: CSR fill, grid-strided (20480 threads) */
    int g = bid * 1024 + t;
    int E4 = E >> 2;
    for (int i = g; i < E4; i += SCAN_BLKS * 1024) {
        int4 s = ((const int4*)src)[i];
        int4 d = ((const int4*)dst)[i];
        g_cedge[g_off[d.x] + atomicAdd(&g_cursor[d.x], 1)] =
            make_int2(s.x, __float_as_int(g_dnsrc[s.x]));
        g_cedge[g_off[d.y] + atomicAdd(&g_cursor[d.y], 1)] =
            make_int2(s.y, __float_as_int(g_dnsrc[s.y]));
        g_cedge[g_off[d.z] + atomicAdd(&g_cursor[d.z], 1)] =
            make_int2(s.z, __float_as_int(g_dnsrc[s.z]));
        g_cedge[g_off[d.w] + atomicAdd(&g_cursor[d.w], 1)] =
            make_int2(s.w, __float_as_int(g_dnsrc[s.w]));
    }
    for (int e = E4 * 4 + g; e < E; e += SCAN_BLKS * 1024) {
        int d = dst[e];
        int s = src[e];
        g_cedge[g_off[d] + atomicAdd(&g_cursor[d], 1)] =
            make_int2(s, __float_as_int(g_dnsrc[s]));
    }
}

/* ---------------- K3: fused fp16 aggregation + LSTM epilogue ------------
   128 threads per node, split into 2 halves of 64.
   Half h processes edges start+h, start+h+2, ... ; each thread owns one
   uint4 (8 halves) of the 1KB node row -> LDG.128 gathers.              */
__global__ void __launch_bounds__(128) k_aggf(const float* __restrict__ bg,
                                              const float* __restrict__ cprev,
                                              float* __restrict__ out) {
    __shared__ float sc[512];
    int n = blockIdx.x;
    int t = threadIdx.x;
    int h = t >> 6;            /* half 0/1 */
    int q = t & 63;            /* uint4 index within row */
    int start = g_off[n], end = g_off[n + 1];

    float acc[8];
#pragma unroll
    for (int i = 0; i < 8; i++) acc[i] = 0.f;

    const uint4* base = (const uint4*)g_hwh;    /* node row = 64 uint4 */

#define ACC_V(V, SCBITS)                                                       \
    {                                                                          \
        float s_ = __int_as_float(SCBITS);                                     \
        __half2 h0 = reinterpret_cast<__half2&>(V.x);                          \
        __half2 h1 = reinterpret_cast<__half2&>(V.y);                          \
        __half2 h2 = reinterpret_cast<__half2&>(V.z);                          \
        __half2 h3 = reinterpret_cast<__half2&>(V.w);                          \
        float2 f0 = __half22float2(h0);                                        \
        float2 f1 = __half22float2(h1);                                        \
        float2 f2 = __half22float2(h2);                                        \
        float2 f3 = __half22float2(h3);                                        \
        acc[0] = fmaf(f0.x, s_, acc[0]); acc[1] = fmaf(f0.y, s_, acc[1]);      \
        acc[2] = fmaf(f1.x, s_, acc[2]); acc[3] = fmaf(f1.y, s_, acc[3]);      \
        acc[4] = fmaf(f2.x, s_, acc[4]); acc[5] = fmaf(f2.y, s_, acc[5]);      \
        acc[6] = fmaf(f3.x, s_, acc[6]); acc[7] = fmaf(f3.y, s_, acc[7]);      \
    }

    int e = start + h;
    for (; e + 6 < end; e += 8) {
        int2 e0 = g_cedge[e];
        int2 e1 = g_cedge[e + 2];
        int2 e2 = g_cedge[e + 4];
        int2 e3 = g_cedge[e + 6];
        uint4 v0 = base[(size_t)e0.x * 64 + q];
        uint4 v1 = base[(size_t)e1.x * 64 + q];
        uint4 v2 = base[(size_t)e2.x * 64 + q];
        uint4 v3 = base[(size_t)e3.x * 64 + q];
        ACC_V(v0, e0.y)
        ACC_V(v1, e1.y)
        ACC_V(v2, e2.y)
        ACC_V(v3, e3.y)
    }
    for (; e < end; e += 2) {
        int2 ed = g_cedge[e];
        uint4 v = base[(size_t)ed.x * 64 + q];
        ACC_V(v, ed.y)
    }
#undef ACC_V

    /* combine halves through smem */
    if (h == 0) {
#pragma unroll
        for (int i = 0; i < 8; i++) sc[q * 8 + i] = acc[i];
    }
    __syncthreads();
    if (h == 1) {
#pragma unroll
        for (int i = 0; i < 8; i++) sc[q * 8 + i] += acc[i];
    }
    __syncthreads();

    /* LSTM epilogue: thread t owns floats sc[4t..4t+3] */
    float dn = g_dndst[n];
    float4 av = *(const float4*)&sc[t * 4];
    float4 bgv = ((const float4*)bg)[t & 31];
    float4 gv;
    gv.x = av.x * dn + bgv.x;
    gv.y = av.y * dn + bgv.y;
    gv.z = av.z * dn + bgv.z;
    gv.w = av.w * dn + bgv.w;

    const float4* G = (const float4*)g_gates;
    float4 gi = G[0 * 128 + t];
    float4 gf = G[1 * 128 + t];
    float4 go = G[2 * 128 + t];
    float4 gc = G[3 * 128 + t];

    int b = t >> 5;
    size_t p = ((size_t)b * N_NODES + n) * H_DIM + (t & 31) * 4;
    float4 cp = *(const float4*)&cprev[p];

    float4 ho, co;
#define LSTM_COMP(comp)                                              \
    {                                                                \
        float g  = gv.comp;                                          \
        float iv = sig_hw(gi.comp + g);                              \
        float fv = sig_hw(gf.comp + g);                              \
        float ov = sig_hw(go.comp + g);                              \
        float ct = tanh_hw(gc.comp + g);                             \
        float c  = fv * cp.comp + iv * ct;                           \
        co.comp  = c;                                                \
        ho.comp  = ov * tanh_hw(c);                                  \
    }
    LSTM_COMP(x) LSTM_COMP(y) LSTM_COMP(z) LSTM_COMP(w)
#undef LSTM_COMP

    *(float4*)&out[p]       = ho;
    *(float4*)&out[BNH + p] = co;
}

/* ---------------- launch ------------------------------------------------ */
extern "C" void kernel_launch(void* const* d_in, const int* in_sizes, int n_in,
                              void* d_out, int out_size) {
    const float* x     = (const float*)d_in[0];
    const float* hprev = (const float*)d_in[1];
    const float* cprev = (const float*)d_in[2];
    const int*   src   = (const int*)  d_in[3];
    const int*   dst   = (const int*)  d_in[4];
    const float* Wi = (const float*)d_in[5];  const float* bi = (const float*)d_in[6];
    const float* Wf = (const float*)d_in[7];  const float* bf = (const float*)d_in[8];
    const float* Wo = (const float*)d_in[9];  const float* bo = (const float*)d_in[10];
    const float* Wc = (const float*)d_in[11]; const float* bc = (const float*)d_in[12];
    const float* Wg = (const float*)d_in[13]; const float* bg = (const float*)d_in[14];
    int E = in_sizes[3];
    float* out = (float*)d_out;

    cudaFuncSetAttribute(k_fat, cudaFuncAttributeMaxDynamicSharedMemorySize, FAT_SMEM);

    k_zero     <<<(N_NODES + 255) / 256, 256>>>(Wg);
    k_fat      <<<946, 256, FAT_SMEM>>>(hprev, src, dst, E, x,
                                        Wi, bi, Wf, bf, Wo, bo, Wc, bc);
    k_scanfill <<<SCAN_BLKS, 1024>>>(src, dst, E);
    k_aggf     <<<N_NODES, 128>>>(bg, cprev, out);
}

// round 11
// speedup vs baseline: 1.1960x; 1.1960x over previous
#include <cuda_runtime.h>
#include <cuda_fp16.h>
#include <cuda_bf16.h>
#include <mma.h>
#include <cstdint>

#define N_NODES 20000
#define BATCH   4
#define H_DIM   128
#define I_DIM   64
#define E_CAP   320000
#define NODEVEC 512                       /* halves per node, [b][h] */
#define BNH     (BATCH * N_NODES * H_DIM)
#define SCAN_BLKS 20
#define SA_STRIDE 136                     /* smem stride (elems), mult of 8 */
#define FAT_SMEM  (128 * SA_STRIDE * 4)   /* 69632 B: 2 bf16 tiles OR 1 f32 tile */

typedef unsigned long long ull;
using namespace nvcuda;

/* ---------------- device scratch (static, allocation-free) -------------- */
__device__ __align__(16) __half g_hwh[(size_t)N_NODES * NODEVEC]; /* h@Wg (unscaled), fp16 */
__device__ __align__(16) __nv_bfloat16 g_Bbf[H_DIM * H_DIM];      /* bf16(Wg), [k][n] row-major */
__device__ int   g_outcnt[N_NODES];
__device__ int   g_incnt[N_NODES];
__device__ int   g_cursor[N_NODES];
__device__ int   g_off[N_NODES + 1];
__device__ __align__(8) int2 g_cedge[E_CAP];       /* {src, bits(dn_src[src])} */
__device__ float g_dnsrc[N_NODES];
__device__ float g_dndst[N_NODES];
__device__ int   g_bsum[SCAN_BLKS];
__device__ int   g_bpre[SCAN_BLKS + 1];
__device__ int   g_flagA, g_flagB;
__device__ __align__(16) float g_gates[4 * BATCH * H_DIM];        /* [gate][b][h] */

/* ---------------- helpers ---------------------------------------------- */
__device__ __forceinline__ float tanh_hw(float x) {
    float y;
    asm("tanh.approx.f32 %0, %1;" : "=f"(y) : "f"(x));
    return y;
}
__device__ __forceinline__ float sig_hw(float x) {
    return fmaf(tanh_hw(0.5f * x), 0.5f, 0.5f);
}
__device__ __forceinline__ uint4 ldcg128(const uint4* p) {
    uint4 v;
    asm volatile("ld.global.cg.v4.u32 {%0,%1,%2,%3}, [%4];"
                 : "=r"(v.x), "=r"(v.y), "=r"(v.z), "=r"(v.w) : "l"(p));
    return v;
}

/* ---------------- K0: zero counters + build bf16(Wg) -------------------- */
__global__ void k_zero(const float* __restrict__ Wg) {
    int i = blockIdx.x * blockDim.x + threadIdx.x;
    if (i < N_NODES) { g_outcnt[i] = 0; g_incnt[i] = 0; }
    if (i == 0) { g_flagA = 0; g_flagB = 0; }
    if (i < H_DIM * H_DIM) g_Bbf[i] = __float2bfloat16(Wg[i]);
}

/* ---------------- K1 (fat): deg || gates || mm(wmma bf16) ----------------
   256 threads/block. grid = 946:
     bid < 626 : even -> mm tile bid/2 ; odd -> deg block (bid-1)/2
     626..937  : mm tile 313 + (bid-626)
     938..945  : gates block bid-938
------------------------------------------------------------------------- */
__global__ void __launch_bounds__(256) k_fat(
        const float* __restrict__ hprev,
        const int* __restrict__ src, const int* __restrict__ dst, int E,
        const float* __restrict__ x,
        const float* __restrict__ Wi, const float* __restrict__ bi,
        const float* __restrict__ Wf, const float* __restrict__ bf,
        const float* __restrict__ Wo, const float* __restrict__ bo,
        const float* __restrict__ Wc, const float* __restrict__ bc) {
    extern __shared__ unsigned char dsm[];
    int bid = blockIdx.x;
    int t = threadIdx.x;

    int role, rid;                 /* 0=mm 1=deg 2=gates */
    if (bid < 626) {
        if (bid & 1) { role = 1; rid = (bid - 1) >> 1; }
        else         { role = 0; rid = bid >> 1; }
    } else if (bid < 938) { role = 0; rid = 313 + (bid - 626); }
    else                  { role = 2; rid = bid - 938; }

    if (role == 1) {
        /* -------- degree histograms, 4 edges / thread -------- */
        int i = rid * 256 + t;
        int E4 = E >> 2;
        if (i < E4) {
            int4 s = ((const int4*)src)[i];
            int4 d = ((const int4*)dst)[i];
            atomicAdd(&g_outcnt[s.x], 1); atomicAdd(&g_outcnt[s.y], 1);
            atomicAdd(&g_outcnt[s.z], 1); atomicAdd(&g_outcnt[s.w], 1);
            atomicAdd(&g_incnt[d.x], 1);  atomicAdd(&g_incnt[d.y], 1);
            atomicAdd(&g_incnt[d.z], 1);  atomicAdd(&g_incnt[d.w], 1);
        }
        int e = E4 * 4 + i;
        if (e < E) { atomicAdd(&g_outcnt[src[e]], 1); atomicAdd(&g_incnt[dst[e]], 1); }
        return;
    }

    if (role == 2) {
        /* -------- tiny gate GEMVs  x@W + b -------- */
        int tid = rid * 256 + t;
        int g = tid / (BATCH * H_DIM);
        int b = (tid % (BATCH * H_DIM)) / H_DIM;
        int j = tid % H_DIM;
        const float* W; const float* bb;
        switch (g) {
            case 0:  W = Wi; bb = bi; break;
            case 1:  W = Wf; bb = bf; break;
            case 2:  W = Wo; bb = bo; break;
            default: W = Wc; bb = bc; break;
        }
        float s = bb[j];
        const float* xr = x + b * I_DIM;
#pragma unroll 8
        for (int k = 0; k < I_DIM; k++) s += xr[k] * W[k * H_DIM + j];
        g_gates[tid] = s;
        return;
    }

    /* -------- mm: g_hwh[tile rows] = bf16(h_prev) @ bf16(Wg) via HMMA ---- */
    {
        __nv_bfloat16* sA = (__nv_bfloat16*)dsm;                  /* 128 x 136 */
        __nv_bfloat16* sB = sA + 128 * SA_STRIDE;                 /* 128 x 136 */
        float*         sC = (float*)dsm;                          /* reuse      */

        int w   = t >> 5;                    /* warp 0..7: rows [16w,16w+16) */
        int r0  = rid * 128;

        /* A tile: 128 rows x 128 k fp32 -> bf16, stride 136 */
        {
            const float4* h4 = (const float4*)hprev;
#pragma unroll
            for (int i = 0; i < 16; i++) {
                int idx = t + i * 256;       /* 4096 float4 */
                int row = idx >> 5;
                int kq  = idx & 31;
                float4 v = h4[(size_t)(r0 + row) * 32 + kq];
                __nv_bfloat162 b01 = __floats2bfloat162_rn(v.x, v.y);
                __nv_bfloat162 b23 = __floats2bfloat162_rn(v.z, v.w);
                uint2 st;
                st.x = reinterpret_cast<unsigned&>(b01);
                st.y = reinterpret_cast<unsigned&>(b23);
                *(uint2*)&sA[row * SA_STRIDE + kq * 4] = st;
            }
        }
        /* B tile: bf16(Wg) [k][n], global stride 128 -> smem stride 136 */
        {
            const uint2* gb = (const uint2*)g_Bbf;                /* 4096 x 4 bf16 */
#pragma unroll
            for (int i = 0; i < 16; i++) {
                int idx = t + i * 256;
                int row = idx >> 5;
                int c4  = idx & 31;
                *(uint2*)&sB[row * SA_STRIDE + c4 * 4] = gb[idx];
            }
        }
        __syncthreads();

        wmma::fragment<wmma::accumulator, 16, 16, 16, float> acc[8];
#pragma unroll
        for (int nc = 0; nc < 8; nc++) wmma::fill_fragment(acc[nc], 0.0f);

        wmma::fragment<wmma::matrix_a, 16, 16, 16, __nv_bfloat16, wmma::row_major> af;
        wmma::fragment<wmma::matrix_b, 16, 16, 16, __nv_bfloat16, wmma::row_major> bf_;
#pragma unroll
        for (int ks = 0; ks < 8; ks++) {
            wmma::load_matrix_sync(af, &sA[(w * 16) * SA_STRIDE + ks * 16], SA_STRIDE);
#pragma unroll
            for (int nc = 0; nc < 8; nc++) {
                wmma::load_matrix_sync(bf_, &sB[(ks * 16) * SA_STRIDE + nc * 16], SA_STRIDE);
                wmma::mma_sync(acc[nc], af, bf_, acc[nc]);
            }
        }
        __syncthreads();                    /* done reading sA/sB */

#pragma unroll
        for (int nc = 0; nc < 8; nc++)
            wmma::store_matrix_sync(&sC[(w * 16) * SA_STRIDE + nc * 16], acc[nc],
                                    SA_STRIDE, wmma::mem_row_major);
        __syncthreads();

        /* write out as fp16: thread t -> row t>>1, cols [(t&1)*64, +64) */
        {
            int row = t >> 1;
            int c0  = (t & 1) * 64;
            int m = r0 + row;
            int b = m / N_NODES;
            int n = m - b * N_NODES;
            __half* dstp = g_hwh + (size_t)n * NODEVEC + b * H_DIM + c0;
            const float* srcp = &sC[row * SA_STRIDE + c0];
#pragma unroll
            for (int q = 0; q < 8; q++) {
                float4 v0 = *(const float4*)&srcp[q * 8];
                float4 v1 = *(const float4*)&srcp[q * 8 + 4];
                __half2 h0 = __floats2half2_rn(v0.x, v0.y);
                __half2 h1 = __floats2half2_rn(v0.z, v0.w);
                __half2 h2 = __floats2half2_rn(v1.x, v1.y);
                __half2 h3 = __floats2half2_rn(v1.z, v1.w);
                uint4 st;
                st.x = reinterpret_cast<unsigned&>(h0);
                st.y = reinterpret_cast<unsigned&>(h1);
                st.z = reinterpret_cast<unsigned&>(h2);
                st.w = reinterpret_cast<unsigned&>(h3);
                *(uint4*)(dstp + q * 8) = st;
            }
        }
    }
}

/* ---------------- K2: fused 3-phase scan (20 co-resident blocks) -------- */
__global__ void __launch_bounds__(1024) k_scan() {
    __shared__ int sm[1024];
    int bid = blockIdx.x;
    int t = threadIdx.x;
    int idx = bid * 1024 + t;
    int cnt = (idx < N_NODES) ? g_incnt[idx] : 0;

    sm[t] = cnt;
    __syncthreads();
#pragma unroll
    for (int s = 512; s; s >>= 1) {
        if (t < s) sm[t] += sm[t + s];
        __syncthreads();
    }
    if (t == 0) {
        g_bsum[bid] = sm[0];
        __threadfence();
        atomicAdd(&g_flagA, 1);
    }

    if (bid == 0 && t == 0) {
        while (*((volatile int*)&g_flagA) < SCAN_BLKS) { }
        __threadfence();
        int run = 0;
        for (int b = 0; b < SCAN_BLKS; b++) {
            g_bpre[b] = run;
            run += *((volatile int*)&g_bsum[b]);
        }
        g_off[N_NODES] = run;
        __threadfence();
        atomicExch(&g_flagB, 1);
    }
    if (t == 0) {
        while (*((volatile int*)&g_flagB) == 0) { }
    }
    __syncthreads();
    int base = *((volatile int*)&g_bpre[bid]);

    sm[t] = cnt;
    __syncthreads();
#pragma unroll
    for (int off = 1; off < 1024; off <<= 1) {
        int u = (t >= off) ? sm[t - off] : 0;
        __syncthreads();
        sm[t] += u;
        __syncthreads();
    }
    if (idx < N_NODES) {
        int incl = sm[t];
        g_off[idx]    = base + incl - cnt;
        g_dndst[idx]  = rsqrtf((float)max(cnt, 1));
        g_dnsrc[idx]  = rsqrtf((float)max(g_outcnt[idx], 1));
        g_cursor[idx] = 0;
    }
}

/* ---------------- K3: CSR fill, 1 edge / thread (max MLP) ---------------- */
__global__ void k_fill(const int* __restrict__ src, const int* __restrict__ dst, int E) {
    int e = blockIdx.x * blockDim.x + threadIdx.x;
    if (e < E) {
        int d = dst[e];
        int s = src[e];
        g_cedge[g_off[d] + atomicAdd(&g_cursor[d], 1)] =
            make_int2(s, __float_as_int(g_dnsrc[s]));
    }
}

/* ---------------- K4: fused fp16 aggregation + LSTM epilogue ------------
   128 threads per node, 2 halves of 64; half h takes edges start+h, +2...
   Each thread owns one uint4 (8 halves) of the 1KB row; 8-edge unroll,
   ld.global.cg (skip L1 allocation - rows have no intra-SM reuse).       */
__global__ void __launch_bounds__(128) k_aggf(const float* __restrict__ bg,
                                              const float* __restrict__ cprev,
                                              float* __restrict__ out) {
    __shared__ float sc[512];
    int n = blockIdx.x;
    int t = threadIdx.x;
    int h = t >> 6;            /* half 0/1 */
    int q = t & 63;            /* uint4 index within row */
    int start = g_off[n], end = g_off[n + 1];

    float acc[8];
#pragma unroll
    for (int i = 0; i < 8; i++) acc[i] = 0.f;

    const uint4* base = (const uint4*)g_hwh;    /* node row = 64 uint4 */

#define ACC_V(V, SCBITS)                                                       \
    {                                                                          \
        float s_ = __int_as_float(SCBITS);                                     \
        float2 f0 = __half22float2(reinterpret_cast<__half2&>(V.x));           \
        float2 f1 = __half22float2(reinterpret_cast<__half2&>(V.y));           \
        float2 f2 = __half22float2(reinterpret_cast<__half2&>(V.z));           \
        float2 f3 = __half22float2(reinterpret_cast<__half2&>(V.w));           \
        acc[0] = fmaf(f0.x, s_, acc[0]); acc[1] = fmaf(f0.y, s_, acc[1]);      \
        acc[2] = fmaf(f1.x, s_, acc[2]); acc[3] = fmaf(f1.y, s_, acc[3]);      \
        acc[4] = fmaf(f2.x, s_, acc[4]); acc[5] = fmaf(f2.y, s_, acc[5]);      \
        acc[6] = fmaf(f3.x, s_, acc[6]); acc[7] = fmaf(f3.y, s_, acc[7]);      \
    }

    int e = start + h;
    /* 8 edges (stride 2) in flight per iteration */
    for (; e + 14 < end; e += 16) {
        int2 ed[8];
        uint4 v[8];
#pragma unroll
        for (int i = 0; i < 8; i++) ed[i] = g_cedge[e + 2 * i];
#pragma unroll
        for (int i = 0; i < 8; i++) v[i] = ldcg128(base + (size_t)ed[i].x * 64 + q);
#pragma unroll
        for (int i = 0; i < 8; i++) ACC_V(v[i], ed[i].y)
    }
    for (; e < end; e += 2) {
        int2 ed = g_cedge[e];
        uint4 v = ldcg128(base + (size_t)ed.x * 64 + q);
        ACC_V(v, ed.y)
    }
#undef ACC_V

    /* combine halves through smem */
    if (h == 0) {
#pragma unroll
        for (int i = 0; i < 8; i++) sc[q * 8 + i] = acc[i];
    }
    __syncthreads();
    if (h == 1) {
#pragma unroll
        for (int i = 0; i < 8; i++) sc[q * 8 + i] += acc[i];
    }
    __syncthreads();

    /* LSTM epilogue: thread t owns floats sc[4t..4t+3] */
    float dn = g_dndst[n];
    float4 av = *(const float4*)&sc[t * 4];
    float4 bgv = ((const float4*)bg)[t & 31];
    float4 gv;
    gv.x = av.x * dn + bgv.x;
    gv.y = av.y * dn + bgv.y;
    gv.z = av.z * dn + bgv.z;
    gv.w = av.w * dn + bgv.w;

    const float4* G = (const float4*)g_gates;
    float4 gi = G[0 * 128 + t];
    float4 gf = G[1 * 128 + t];
    float4 go = G[2 * 128 + t];
    float4 gc = G[3 * 128 + t];

    int b = t >> 5;
    size_t p = ((size_t)b * N_NODES + n) * H_DIM + (t & 31) * 4;
    float4 cp = *(const float4*)&cprev[p];

    float4 ho, co;
#define LSTM_COMP(comp)                                              \
    {                                                                \
        float g  = gv.comp;                                          \
        float iv = sig_hw(gi.comp + g);                              \
        float fv = sig_hw(gf.comp + g);                              \
        float ov = sig_hw(go.comp + g);                              \
        float ct = tanh_hw(gc.comp + g);                             \
        float c  = fv * cp.comp + iv * ct;                           \
        co.comp  = c;                                                \
        ho.comp  = ov * tanh_hw(c);                                  \
    }
    LSTM_COMP(x) LSTM_COMP(y) LSTM_COMP(z) LSTM_COMP(w)
#undef LSTM_COMP

    *(float4*)&out[p]       = ho;
    *(float4*)&out[BNH + p] = co;
}

/* ---------------- launch ------------------------------------------------ */
extern "C" void kernel_launch(void* const* d_in, const int* in_sizes, int n_in,
                              void* d_out, int out_size) {
    const float* x     = (const float*)d_in[0];
    const float* hprev = (const float*)d_in[1];
    const float* cprev = (const float*)d_in[2];
    const int*   src   = (const int*)  d_in[3];
    const int*   dst   = (const int*)  d_in[4];
    const float* Wi = (const float*)d_in[5];  const float* bi = (const float*)d_in[6];
    const float* Wf = (const float*)d_in[7];  const float* bf = (const float*)d_in[8];
    const float* Wo = (const float*)d_in[9];  const float* bo = (const float*)d_in[10];
    const float* Wc = (const float*)d_in[11]; const float* bc = (const float*)d_in[12];
    const float* Wg = (const float*)d_in[13]; const float* bg = (const float*)d_in[14];
    int E = in_sizes[3];
    float* out = (float*)d_out;

    cudaFuncSetAttribute(k_fat, cudaFuncAttributeMaxDynamicSharedMemorySize, FAT_SMEM);

    k_zero <<<(N_NODES + 255) / 256, 256>>>(Wg);
    k_fat  <<<946, 256, FAT_SMEM>>>(hprev, src, dst, E, x,
                                    Wi, bi, Wf, bf, Wo, bo, Wc, bc);
    k_scan <<<SCAN_BLKS, 1024>>>();
    k_fill <<<(E + 255) / 256, 256>>>(src, dst, E);
    k_aggf <<<N_NODES, 128>>>(bg, cprev, out);
}

// round 12
// speedup vs baseline: 1.2737x; 1.0650x over previous
#include <cuda_runtime.h>
#include <cuda_fp16.h>
#include <cuda_bf16.h>
#include <mma.h>
#include <cstdint>

#define N_NODES 20000
#define BATCH   4
#define H_DIM   128
#define I_DIM   64
#define E_CAP   320000
#define NODEVEC 512                       /* halves per node, [b][h] */
#define BNH     (BATCH * N_NODES * H_DIM)
#define NSCAN   80                        /* scan role blocks (256 thr each) */
#define NMM     625                       /* 80000 rows / 128 */
#define NGATES  8
#define SA_STRIDE 136                     /* smem stride (elems), mult of 8 */
#define FAT_SMEM  (128 * SA_STRIDE * 4)   /* 69632 B */

typedef unsigned long long ull;
using namespace nvcuda;

/* ---------------- device scratch (static, allocation-free) --------------
   NOTE: counters/flags are left ZEROED by k_aggf's tail each call, so every
   launch (first one via zero-init of device globals) starts clean.        */
__device__ __align__(16) __half g_hwh[(size_t)N_NODES * NODEVEC]; /* h@Wg (unscaled), fp16 */
__device__ int   g_outcnt[N_NODES];
__device__ int   g_incnt[N_NODES];
__device__ int   g_cursor[N_NODES];
__device__ int   g_off[N_NODES + 1];
__device__ __align__(8) int2 g_cedge[E_CAP];       /* {src, bits(dn_src[src])} */
__device__ float g_dnsrc[N_NODES];
__device__ float g_dndst[N_NODES];
__device__ int   g_bsum[NSCAN];
__device__ int   g_bpre[NSCAN];
__device__ int   g_fDeg, g_fA, g_fB, g_fScan;
__device__ __align__(16) float g_gates[4 * BATCH * H_DIM];        /* [gate][b][h] */

/* ---------------- helpers ---------------------------------------------- */
__device__ __forceinline__ float tanh_hw(float x) {
    float y;
    asm("tanh.approx.f32 %0, %1;" : "=f"(y) : "f"(x));
    return y;
}
__device__ __forceinline__ float sig_hw(float x) {
    return fmaf(tanh_hw(0.5f * x), 0.5f, 0.5f);
}
__device__ __forceinline__ uint4 ldcg128(const uint4* p) {
    uint4 v;
    asm volatile("ld.global.cg.v4.u32 {%0,%1,%2,%3}, [%4];"
                 : "=r"(v.x), "=r"(v.y), "=r"(v.z), "=r"(v.w) : "l"(p));
    return v;
}
__device__ __forceinline__ int ldvol(const int* p) {
    return *((volatile const int*)p);
}

/* ---------------- K1 (fat): deg -> scan -> {mm, gates} -> fill -----------
   256 threads/block. Bid-ordered phases with flag handshakes:
     [0, b1)      deg    (no deps)
     [b1, b2)     scan   (waits g_fDeg == ndeg)
     [b2, b3)     mm     (no deps)
     [b3, b4)     gates  (no deps)
     [b4, nb)     fill   (waits g_fScan == NSCAN)
   Consumers have strictly higher bids than producers -> wave-1 bid-order
   scheduling guarantees producers are resident-or-retired -> no deadlock. */
__global__ void __launch_bounds__(256) k_fat(
        const float* __restrict__ hprev, const float* __restrict__ Wg,
        const int* __restrict__ src, const int* __restrict__ dst, int E, int ndeg,
        const float* __restrict__ x,
        const float* __restrict__ Wi, const float* __restrict__ bi,
        const float* __restrict__ Wf, const float* __restrict__ bf,
        const float* __restrict__ Wo, const float* __restrict__ bo,
        const float* __restrict__ Wc, const float* __restrict__ bc) {
    extern __shared__ unsigned char dsm[];
    int bid = blockIdx.x;
    int t = threadIdx.x;
    int b1 = ndeg, b2 = b1 + NSCAN, b3 = b2 + NMM, b4 = b3 + NGATES;

    /* ================= role: degree histograms ================= */
    if (bid < b1) {
        int rid = bid;
        int i = rid * 256 + t;
        int E4 = E >> 2;
        if (i < E4) {
            int4 s = ((const int4*)src)[i];
            int4 d = ((const int4*)dst)[i];
            atomicAdd(&g_outcnt[s.x], 1); atomicAdd(&g_outcnt[s.y], 1);
            atomicAdd(&g_outcnt[s.z], 1); atomicAdd(&g_outcnt[s.w], 1);
            atomicAdd(&g_incnt[d.x], 1);  atomicAdd(&g_incnt[d.y], 1);
            atomicAdd(&g_incnt[d.z], 1);  atomicAdd(&g_incnt[d.w], 1);
        }
        int e = E4 * 4 + i;
        if (e < E) { atomicAdd(&g_outcnt[src[e]], 1); atomicAdd(&g_incnt[dst[e]], 1); }
        __syncthreads();
        if (t == 0) { __threadfence(); atomicAdd(&g_fDeg, 1); }
        return;
    }

    /* ================= role: scan (80 blocks x 256 nodes) ================= */
    if (bid < b2) {
        int rid = bid - b1;
        int* sm = (int*)dsm;
        if (t == 0) { while (ldvol(&g_fDeg) < ndeg) { } }
        __syncthreads();
        __threadfence();

        int idx = rid * 256 + t;
        int cnt = (idx < N_NODES) ? g_incnt[idx] : 0;

        /* block sum */
        sm[t] = cnt;
        __syncthreads();
#pragma unroll
        for (int s = 128; s; s >>= 1) {
            if (t < s) sm[t] += sm[t + s];
            __syncthreads();
        }
        if (t == 0) {
            g_bsum[rid] = sm[0];
            __threadfence();
            atomicAdd(&g_fA, 1);
        }
        /* leader scans the 80 partials */
        if (rid == 0 && t == 0) {
            while (ldvol(&g_fA) < NSCAN) { }
            __threadfence();
            int run = 0;
            for (int b = 0; b < NSCAN; b++) {
                g_bpre[b] = run;
                run += ldvol(&g_bsum[b]);
            }
            g_off[N_NODES] = run;
            __threadfence();
            atomicExch(&g_fB, 1);
        }
        if (t == 0) { while (ldvol(&g_fB) == 0) { } }
        __syncthreads();
        __threadfence();
        int base = ldvol(&g_bpre[rid]);

        /* intra-block inclusive scan (Hillis-Steele, 256) */
        sm[t] = cnt;
        __syncthreads();
#pragma unroll
        for (int off = 1; off < 256; off <<= 1) {
            int u = (t >= off) ? sm[t - off] : 0;
            __syncthreads();
            sm[t] += u;
            __syncthreads();
        }
        if (idx < N_NODES) {
            int incl = sm[t];
            g_off[idx]    = base + incl - cnt;
            g_dndst[idx]  = rsqrtf((float)max(cnt, 1));
            g_dnsrc[idx]  = rsqrtf((float)max(g_incnt[idx] ? g_outcnt[idx] : g_outcnt[idx], 1));
            g_cursor[idx] = 0;
        }
        __syncthreads();
        if (t == 0) { __threadfence(); atomicAdd(&g_fScan, 1); }
        return;
    }

    /* ================= role: mm (wmma bf16 128x128x128) ================= */
    if (bid < b3) {
        int rid = bid - b2;
        __nv_bfloat16* sA = (__nv_bfloat16*)dsm;                  /* 128 x 136 */
        __nv_bfloat16* sB = sA + 128 * SA_STRIDE;                 /* 128 x 136 */
        float*         sC = (float*)dsm;                          /* reuse      */

        int w  = t >> 5;
        int r0 = rid * 128;

        /* A tile: 128 rows x 128 k fp32 -> bf16 */
        {
            const float4* h4 = (const float4*)hprev;
#pragma unroll
            for (int i = 0; i < 16; i++) {
                int idx = t + i * 256;
                int row = idx >> 5;
                int kq  = idx & 31;
                float4 v = h4[(size_t)(r0 + row) * 32 + kq];
                __nv_bfloat162 b01 = __floats2bfloat162_rn(v.x, v.y);
                __nv_bfloat162 b23 = __floats2bfloat162_rn(v.z, v.w);
                uint2 st;
                st.x = reinterpret_cast<unsigned&>(b01);
                st.y = reinterpret_cast<unsigned&>(b23);
                *(uint2*)&sA[row * SA_STRIDE + kq * 4] = st;
            }
        }
        /* B tile: Wg fp32 [k][n] -> bf16 smem (L2-resident source) */
        {
            const float4* w4 = (const float4*)Wg;
#pragma unroll
            for (int i = 0; i < 16; i++) {
                int idx = t + i * 256;
                int row = idx >> 5;
                int c4  = idx & 31;
                float4 v = w4[row * 32 + c4];
                __nv_bfloat162 b01 = __floats2bfloat162_rn(v.x, v.y);
                __nv_bfloat162 b23 = __floats2bfloat162_rn(v.z, v.w);
                uint2 st;
                st.x = reinterpret_cast<unsigned&>(b01);
                st.y = reinterpret_cast<unsigned&>(b23);
                *(uint2*)&sB[row * SA_STRIDE + c4 * 4] = st;
            }
        }
        __syncthreads();

        wmma::fragment<wmma::accumulator, 16, 16, 16, float> acc[8];
#pragma unroll
        for (int nc = 0; nc < 8; nc++) wmma::fill_fragment(acc[nc], 0.0f);

        wmma::fragment<wmma::matrix_a, 16, 16, 16, __nv_bfloat16, wmma::row_major> af;
        wmma::fragment<wmma::matrix_b, 16, 16, 16, __nv_bfloat16, wmma::row_major> bf_;
#pragma unroll
        for (int ks = 0; ks < 8; ks++) {
            wmma::load_matrix_sync(af, &sA[(w * 16) * SA_STRIDE + ks * 16], SA_STRIDE);
#pragma unroll
            for (int nc = 0; nc < 8; nc++) {
                wmma::load_matrix_sync(bf_, &sB[(ks * 16) * SA_STRIDE + nc * 16], SA_STRIDE);
                wmma::mma_sync(acc[nc], af, bf_, acc[nc]);
            }
        }
        __syncthreads();

#pragma unroll
        for (int nc = 0; nc < 8; nc++)
            wmma::store_matrix_sync(&sC[(w * 16) * SA_STRIDE + nc * 16], acc[nc],
                                    SA_STRIDE, wmma::mem_row_major);
        __syncthreads();

        /* write fp16: thread t -> row t>>1, cols [(t&1)*64, +64) */
        {
            int row = t >> 1;
            int c0  = (t & 1) * 64;
            int m = r0 + row;
            int b = m / N_NODES;
            int n = m - b * N_NODES;
            __half* dstp = g_hwh + (size_t)n * NODEVEC + b * H_DIM + c0;
            const float* srcp = &sC[row * SA_STRIDE + c0];
#pragma unroll
            for (int q = 0; q < 8; q++) {
                float4 v0 = *(const float4*)&srcp[q * 8];
                float4 v1 = *(const float4*)&srcp[q * 8 + 4];
                __half2 h0 = __floats2half2_rn(v0.x, v0.y);
                __half2 h1 = __floats2half2_rn(v0.z, v0.w);
                __half2 h2 = __floats2half2_rn(v1.x, v1.y);
                __half2 h3 = __floats2half2_rn(v1.z, v1.w);
                uint4 st;
                st.x = reinterpret_cast<unsigned&>(h0);
                st.y = reinterpret_cast<unsigned&>(h1);
                st.z = reinterpret_cast<unsigned&>(h2);
                st.w = reinterpret_cast<unsigned&>(h3);
                *(uint4*)(dstp + q * 8) = st;
            }
        }
        return;
    }

    /* ================= role: gate GEMVs ================= */
    if (bid < b4) {
        int tid = (bid - b3) * 256 + t;
        int g = tid / (BATCH * H_DIM);
        int b = (tid % (BATCH * H_DIM)) / H_DIM;
        int j = tid % H_DIM;
        const float* W; const float* bb;
        switch (g) {
            case 0:  W = Wi; bb = bi; break;
            case 1:  W = Wf; bb = bf; break;
            case 2:  W = Wo; bb = bo; break;
            default: W = Wc; bb = bc; break;
        }
        float s = bb[j];
        const float* xr = x + b * I_DIM;
#pragma unroll 8
        for (int k = 0; k < I_DIM; k++) s += xr[k] * W[k * H_DIM + j];
        g_gates[tid] = s;
        return;
    }

    /* ================= role: CSR fill (1 edge / thread) ================= */
    {
        int rid = bid - b4;
        if (t == 0) { while (ldvol(&g_fScan) < NSCAN) { } }
        __syncthreads();
        __threadfence();
        int e = rid * 256 + t;
        if (e < E) {
            int d = dst[e];
            int s = src[e];
            g_cedge[g_off[d] + atomicAdd(&g_cursor[d], 1)] =
                make_int2(s, __float_as_int(g_dnsrc[s]));
        }
    }
}

/* ---------------- K2: fused fp16 aggregation + LSTM epilogue ------------ */
__global__ void __launch_bounds__(128) k_aggf(const float* __restrict__ bg,
                                              const float* __restrict__ cprev,
                                              float* __restrict__ out) {
    __shared__ float sc[512];
    int n = blockIdx.x;
    int t = threadIdx.x;
    int h = t >> 6;            /* half 0/1 */
    int q = t & 63;            /* uint4 index within row */
    int start = g_off[n], end = g_off[n + 1];

    float acc[8];
#pragma unroll
    for (int i = 0; i < 8; i++) acc[i] = 0.f;

    const uint4* base = (const uint4*)g_hwh;    /* node row = 64 uint4 */

#define ACC_V(V, SCBITS)                                                       \
    {                                                                          \
        float s_ = __int_as_float(SCBITS);                                     \
        float2 f0 = __half22float2(reinterpret_cast<__half2&>(V.x));           \
        float2 f1 = __half22float2(reinterpret_cast<__half2&>(V.y));           \
        float2 f2 = __half22float2(reinterpret_cast<__half2&>(V.z));           \
        float2 f3 = __half22float2(reinterpret_cast<__half2&>(V.w));           \
        acc[0] = fmaf(f0.x, s_, acc[0]); acc[1] = fmaf(f0.y, s_, acc[1]);      \
        acc[2] = fmaf(f1.x, s_, acc[2]); acc[3] = fmaf(f1.y, s_, acc[3]);      \
        acc[4] = fmaf(f2.x, s_, acc[4]); acc[5] = fmaf(f2.y, s_, acc[5]);      \
        acc[6] = fmaf(f3.x, s_, acc[6]); acc[7] = fmaf(f3.y, s_, acc[7]);      \
    }

    int e = start + h;
    for (; e + 14 < end; e += 16) {
        int2 ed[8];
        uint4 v[8];
#pragma unroll
        for (int i = 0; i < 8; i++) ed[i] = g_cedge[e + 2 * i];
#pragma unroll
        for (int i = 0; i < 8; i++) v[i] = ldcg128(base + (size_t)ed[i].x * 64 + q);
#pragma unroll
        for (int i = 0; i < 8; i++) ACC_V(v[i], ed[i].y)
    }
    for (; e < end; e += 2) {
        int2 ed = g_cedge[e];
        uint4 v = ldcg128(base + (size_t)ed.x * 64 + q);
        ACC_V(v, ed.y)
    }
#undef ACC_V

    /* combine halves through smem */
    if (h == 0) {
#pragma unroll
        for (int i = 0; i < 8; i++) sc[q * 8 + i] = acc[i];
    }
    __syncthreads();
    if (h == 1) {
#pragma unroll
        for (int i = 0; i < 8; i++) sc[q * 8 + i] += acc[i];
    }
    __syncthreads();

    /* LSTM epilogue: thread t owns floats sc[4t..4t+3] */
    float dn = g_dndst[n];
    float4 av = *(const float4*)&sc[t * 4];
    float4 bgv = ((const float4*)bg)[t & 31];
    float4 gv;
    gv.x = av.x * dn + bgv.x;
    gv.y = av.y * dn + bgv.y;
    gv.z = av.z * dn + bgv.z;
    gv.w = av.w * dn + bgv.w;

    const float4* G = (const float4*)g_gates;
    float4 gi = G[0 * 128 + t];
    float4 gf = G[1 * 128 + t];
    float4 go = G[2 * 128 + t];
    float4 gc = G[3 * 128 + t];

    int b = t >> 5;
    size_t p = ((size_t)b * N_NODES + n) * H_DIM + (t & 31) * 4;
    float4 cp = *(const float4*)&cprev[p];

    float4 ho, co;
#define LSTM_COMP(comp)                                              \
    {                                                                \
        float g  = gv.comp;                                          \
        float iv = sig_hw(gi.comp + g);                              \
        float fv = sig_hw(gf.comp + g);                              \
        float ov = sig_hw(go.comp + g);                              \
        float ct = tanh_hw(gc.comp + g);                             \
        float c  = fv * cp.comp + iv * ct;                           \
        co.comp  = c;                                                \
        ho.comp  = ov * tanh_hw(c);                                  \
    }
    LSTM_COMP(x) LSTM_COMP(y) LSTM_COMP(z) LSTM_COMP(w)
#undef LSTM_COMP

    *(float4*)&out[p]       = ho;
    *(float4*)&out[BNH + p] = co;

    /* tail: leave counters/flags zero for the next call (deterministic) */
    if (t == 0) { g_outcnt[n] = 0; g_incnt[n] = 0; }
    if (n == 0 && t == 1) { g_fDeg = 0; g_fA = 0; g_fB = 0; g_fScan = 0; }
}

/* ---------------- launch ------------------------------------------------ */
extern "C" void kernel_launch(void* const* d_in, const int* in_sizes, int n_in,
                              void* d_out, int out_size) {
    const float* x     = (const float*)d_in[0];
    const float* hprev = (const float*)d_in[1];
    const float* cprev = (const float*)d_in[2];
    const int*   src   = (const int*)  d_in[3];
    const int*   dst   = (const int*)  d_in[4];
    const float* Wi = (const float*)d_in[5];  const float* bi = (const float*)d_in[6];
    const float* Wf = (const float*)d_in[7];  const float* bf = (const float*)d_in[8];
    const float* Wo = (const float*)d_in[9];  const float* bo = (const float*)d_in[10];
    const float* Wc = (const float*)d_in[11]; const float* bc = (const float*)d_in[12];
    const float* Wg = (const float*)d_in[13]; const float* bg = (const float*)d_in[14];
    int E = in_sizes[3];
    float* out = (float*)d_out;

    int ndeg  = ((E >> 2) + 255) / 256;            /* 313  */
    int nfill = (E + 255) / 256;                   /* 1250 */
    int nb    = ndeg + NSCAN + NMM + NGATES + nfill;

    cudaFuncSetAttribute(k_fat, cudaFuncAttributeMaxDynamicSharedMemorySize, FAT_SMEM);

    k_fat  <<<nb, 256, FAT_SMEM>>>(hprev, Wg, src, dst, E, ndeg, x,
                                   Wi, bi, Wf, bf, Wo, bo, Wc, bc);
    k_aggf <<<N_NODES, 128>>>(bg, cprev, out);
}